// round 6
// baseline (speedup 1.0000x reference)
#include <cuda_runtime.h>
#include <cuda_fp16.h>
#include <cstdint>

#define DINLINE __device__ __forceinline__

// ---------------- problem constants ----------------
constexpr int NB = 16, CINC = 512, COUTC = 512;
constexpr int HWP = 64 * 64;            // 4096
constexpr int M_TOTAL = NB * HWP;       // 65536
constexpr int KTAPS = 9;

// GEMM tiling
constexpr int TM = 128;                 // pixels per tile (2 image rows)
constexpr int TN = 128;                 // cout per tile
constexpr int NCHUNKS = KTAPS * (CINC / 64);   // 72 chunks of KC=64
constexpr int CTHREADS = 256;
constexpr int STAGES = 4;

// xpk plane: 128 guard rows + 65536 + 128 guard rows
constexpr int PLANE = 128 + M_TOTAL + 128;     // 65792

// SMEM: per stage A 128x128B (16KB) + B 128x128B (16KB)
constexpr int STB = 32768;
constexpr int OFF_MBAR = STAGES * STB;         // 131072
constexpr int SMEM_TOTAL = OFF_MBAR + 128;     // 131200

constexpr float WSCALE    = 0.014731391274719738f;   // 1/sqrt(9*512)
constexpr float WSCALE2   = 1.0f / 4608.0f;
constexpr float INV_SQRTW = 0.044194173824159216f;   // 1/sqrt(512)
constexpr float LRELU_G   = 1.4142135623730951f;

// ---------------- scratch (device globals: allocation-free) ----------------
__device__ __align__(128) __half g_xpk[(size_t)8 * PLANE * 64];        // [cc][row][64ci] swizzled
__device__ __align__(128) __half g_wpk[(size_t)KTAPS * 8 * COUTC * 64];// [tap][cc][co][64ci] swizzled
__device__ __align__(128) float  g_s[NB * CINC];
__device__ __align__(128) float  g_wsq[CINC * COUTC];
__device__ __align__(128) float  g_d[NB * COUTC];

// ---------------- PTX helpers ----------------
DINLINE uint32_t smem_u32(const void* p) {
    uint32_t a;
    asm("{ .reg .u64 t; cvta.to.shared.u64 t, %1; cvt.u32.u64 %0, t; }" : "=r"(a) : "l"(p));
    return a;
}
DINLINE void mbar_init(uint32_t mbar, uint32_t cnt) {
    asm volatile("mbarrier.init.shared.b64 [%0], %1;" :: "r"(mbar), "r"(cnt) : "memory");
}
DINLINE void mbar_expect_tx(uint32_t mbar, uint32_t tx) {
    asm volatile("mbarrier.arrive.expect_tx.shared.b64 _, [%0], %1;" :: "r"(mbar), "r"(tx) : "memory");
}
DINLINE void mbar_wait(uint32_t mbar, uint32_t parity) {
    asm volatile(
        "{\n\t.reg .pred P;\n\t"
        "WL_%=:\n\t"
        "mbarrier.try_wait.parity.acquire.cta.shared::cta.b64 P, [%0], %1, 0x989680;\n\t"
        "@P bra.uni WD_%=;\n\t"
        "bra.uni WL_%=;\n\t"
        "WD_%=:\n\t}"
        :: "r"(mbar), "r"(parity) : "memory");
}
DINLINE void bulk_g2s(uint32_t dst, const void* src, uint32_t bytes, uint32_t mbar) {
    asm volatile("cp.async.bulk.shared::cluster.global.mbarrier::complete_tx::bytes "
                 "[%0], [%1], %2, [%3];"
                 :: "r"(dst), "l"(src), "r"(bytes), "r"(mbar) : "memory");
}
DINLINE void fence_async_shared() {
    asm volatile("fence.proxy.async.shared::cta;" ::: "memory");
}

#define LDSM4(r, addr)                                                          \
    asm volatile("ldmatrix.sync.aligned.m8n8.x4.shared.b16 {%0,%1,%2,%3}, [%4];" \
                 : "=r"((r)[0]), "=r"((r)[1]), "=r"((r)[2]), "=r"((r)[3])        \
                 : "r"(addr))

// f16 x f16 -> f16 accumulate (2x rate vs f32 accum)
#define MMAF16(d, a, b0, b1)                                                    \
    asm volatile("mma.sync.aligned.m16n8k16.row.col.f16.f16.f16.f16 "           \
                 "{%0,%1}, {%2,%3,%4,%5}, {%6,%7}, {%0,%1};"                    \
                 : "+r"((d)[0]), "+r"((d)[1])                                    \
                 : "r"((a)[0]), "r"((a)[1]), "r"((a)[2]), "r"((a)[3]),           \
                   "r"(b0), "r"(b1))

// ---------------- prep kernels ----------------
__global__ void k_affine(const float* __restrict__ dl, const float* __restrict__ aw,
                         const float* __restrict__ ab) {
    int n = blockIdx.x, c = threadIdx.x;  // 16 x 512
    const float* row = dl + ((size_t)n * 18 + 8) * 512;
    float acc = 0.f;
    #pragma unroll 4
    for (int w = 0; w < 512; w++) acc += row[w] * __ldg(aw + (size_t)w * 512 + c);
    g_s[n * 512 + c] = acc * INV_SQRTW + ab[c];
}

__global__ void k_wsq(const float* __restrict__ cw) {
    int idx = blockIdx.x * blockDim.x + threadIdx.x;  // 262144
    float acc = 0.f;
    #pragma unroll
    for (int t = 0; t < 9; t++) { float v = __ldg(cw + (size_t)t * 262144 + idx); acc += v * v; }
    g_wsq[idx] = acc;
}

__global__ void k_demod() {
    __shared__ float s2[512];
    int n = blockIdx.x;
    int co = blockIdx.y * 128 + threadIdx.x;
    for (int i = threadIdx.x; i < 512; i += 128) { float v = g_s[n * 512 + i]; s2[i] = v * v; }
    __syncthreads();
    float acc = 0.f;
    #pragma unroll 4
    for (int ci = 0; ci < 512; ci++) acc += s2[ci] * g_wsq[ci * 512 + co];
    g_d[n * 512 + co] = rsqrtf(acc * WSCALE2 + 1e-8f);
}

// xpk[cc][128 + m][word j at j^(m&7)] = fp16(x[m][cc*64 + 8j..8j+7] * s)
// Thread owns one full 128B output row -> coalesced stores, no sector amplification.
__global__ void k_xpk(const float* __restrict__ x) {
    int b = blockIdx.x;                  // 2048 blocks
    int cc = b >> 8;                     // 8 planes
    int m = (b & 255) * 256 + threadIdx.x;
    int n = m >> 12;
    const float4* xp = (const float4*)(x + (size_t)m * 512 + cc * 64);
    const float4* sp = (const float4*)(g_s + n * 512 + cc * 64);
    __half* dst = g_xpk + ((size_t)cc * PLANE + 128 + m) * 64;
    int pm = m & 7;
    uint4 o[8];
    #pragma unroll
    for (int w = 0; w < 8; w++) {
        float4 x0 = __ldg(xp + 2 * w), x1 = __ldg(xp + 2 * w + 1);
        float4 s0 = sp[2 * w], s1 = sp[2 * w + 1];
        __half2 h0 = __floats2half2_rn(x0.x * s0.x, x0.y * s0.y);
        __half2 h1 = __floats2half2_rn(x0.z * s0.z, x0.w * s0.w);
        __half2 h2 = __floats2half2_rn(x1.x * s1.x, x1.y * s1.y);
        __half2 h3 = __floats2half2_rn(x1.z * s1.z, x1.w * s1.w);
        int j = w ^ pm;
        o[j].x = *(uint32_t*)&h0; o[j].y = *(uint32_t*)&h1;
        o[j].z = *(uint32_t*)&h2; o[j].w = *(uint32_t*)&h3;
    }
    #pragma unroll
    for (int j = 0; j < 8; j++) *(uint4*)(dst + j * 8) = o[j];
}

// wpk[tap][cc][co][word j at j^(co&7)] = fp16(conv_w[tap][ci][co] * wscale), transposed
__global__ void k_wpk(const float* __restrict__ cw) {
    __shared__ float tile[64][33];
    int co0 = blockIdx.x * 32, cc = blockIdx.y, tap = blockIdx.z;
    int ci0 = cc * 64;
    int tx = threadIdx.x, ty = threadIdx.y;  // (32, 8)
    #pragma unroll
    for (int r = 0; r < 8; r++) {
        int ci = ty * 8 + r;
        tile[ci][tx] = __ldg(cw + ((size_t)tap * 512 + ci0 + ci) * 512 + co0 + tx);
    }
    __syncthreads();
    int co = co0 + tx, w = ty;
    __half h[8];
    #pragma unroll
    for (int q = 0; q < 8; q++) h[q] = __float2half_rn(tile[w * 8 + q][tx] * WSCALE);
    __half* dst = g_wpk + ((size_t)((tap * 8 + cc) * 512) + co) * 64 + (w ^ (co & 7)) * 8;
    *(uint4*)dst = *(uint4*)h;
}

// ---------------- chunk issue (bulk copies) ----------------
DINLINE void issue_chunk(uint32_t sb, uint32_t mb, int c, int m0, int n0) {
    int stage = c & (STAGES - 1);
    int tap = c >> 3, cc = c & 7;
    int dh = tap / 3 - 1, dw = tap % 3 - 1;
    const __half* srcA = g_xpk + ((size_t)cc * PLANE + 128 + m0 + dh * 64 + dw) * 64;
    const __half* srcB = g_wpk + ((size_t)((tap * 8 + cc) * 512) + n0) * 64;
    uint32_t mbar = mb + stage * 8;
    mbar_expect_tx(mbar, 32768u);
    bulk_g2s(sb + stage * STB,         srcA, 16384u, mbar);
    bulk_g2s(sb + stage * STB + 16384, srcB, 16384u, mbar);
}

// ---------------- main conv kernel ----------------
__global__ void __launch_bounds__(CTHREADS) k_conv(
    const float* __restrict__ conv_b, const float* __restrict__ noise,
    const float* __restrict__ nstr, float* __restrict__ out)
{
    extern __shared__ char smem[];
    uint32_t sb = smem_u32(smem);
    int tid = threadIdx.x, wid = tid >> 5, lane = tid & 31;

    int bid = blockIdx.x;             // 2048 blocks: 512 M-tiles x 4 N-tiles
    int nt = bid & 3, mt = bid >> 2;
    int m0 = mt * TM, n0 = nt * TN;
    int img = m0 >> 12;
    int h0 = (m0 >> 6) & 63;          // tile covers image rows h0, h0+1

    int wm = wid & 1, wn = wid >> 1;  // warp grid 2(M) x 4(N); warp tile 64x32
    uint32_t mb = sb + OFF_MBAR;

    if (tid == 0) {
        #pragma unroll
        for (int s = 0; s < STAGES; s++) mbar_init(mb + s * 8, 1);
    }
    __syncthreads();

    if (tid == 0) {
        issue_chunk(sb, mb, 0, m0, n0);
        issue_chunk(sb, mb, 1, m0, n0);
        issue_chunk(sb, mb, 2, m0, n0);
    }

    float acc[4][4][4];               // f32 master accumulators
    #pragma unroll
    for (int i = 0; i < 4; i++)
        #pragma unroll
        for (int j = 0; j < 4; j++)
            #pragma unroll
            for (int q = 0; q < 4; q++) acc[i][j][q] = 0.f;

    uint32_t hacc[4][4][2];           // f16x2 chunk-pair accumulators

    int rbase = (lane & 7) + ((lane >> 3) & 1) * 8 + wm * 64;
    int ahi   = lane >> 4;
    int bsel  = (lane >> 3) & 1;
    int rB    = wn * 32 + (lane & 7) + ((lane >> 4) & 1) * 8;
    int permB = lane & 7;

    for (int c = 0; c < NCHUNKS; c++) {
        int stage = c & (STAGES - 1);
        mbar_wait(mb + stage * 8, (c >> 2) & 1);

        int tap = c >> 3;
        int dh = tap / 3 - 1, dw = tap % 3 - 1;
        char* ab = smem + stage * STB;

        bool st = false;
        if (dw != 0 && tid < 16) {
            int row = ((dw < 0) ? 0 : 63) + (tid >> 3) * 64;
            ((uint4*)(ab + row * 128))[tid & 7] = make_uint4(0, 0, 0, 0);
            st = true;
        }
        if (h0 + dh < 0) {          // rows 0..63 invalid
            ((uint4*)ab)[tid] = make_uint4(0, 0, 0, 0);
            ((uint4*)ab)[tid + 256] = make_uint4(0, 0, 0, 0);
            st = true;
        }
        if (h0 + 1 + dh > 63) {     // rows 64..127 invalid
            ((uint4*)(ab + 8192))[tid] = make_uint4(0, 0, 0, 0);
            ((uint4*)(ab + 8192))[tid + 256] = make_uint4(0, 0, 0, 0);
            st = true;
        }
        if (st) fence_async_shared();
        __syncthreads();

        if (tid == 0 && c + 3 < NCHUNKS) issue_chunk(sb, mb, c + 3, m0, n0);

        if ((c & 1) == 0) {
            #pragma unroll
            for (int i = 0; i < 4; i++)
                #pragma unroll
                for (int j = 0; j < 4; j++) { hacc[i][j][0] = 0u; hacc[i][j][1] = 0u; }
        }

        uint32_t Ab = sb + stage * STB;
        uint32_t Bb = Ab + 16384;

        #pragma unroll
        for (int kh = 0; kh < 4; kh++) {
            uint32_t a[4][4], b[2][4];
            #pragma unroll
            for (int mf = 0; mf < 4; mf++) {
                int rA = rbase + mf * 16;
                uint32_t ad = Ab + rA * 128 + (((2 * kh + ahi) ^ ((rA + dw) & 7)) * 16);
                LDSM4(a[mf], ad);
            }
            #pragma unroll
            for (int p = 0; p < 2; p++) {
                int r = rB + p * 16;
                uint32_t bd = Bb + r * 128 + (((2 * kh + bsel) ^ permB) * 16);
                LDSM4(b[p], bd);
            }
            #pragma unroll
            for (int mf = 0; mf < 4; mf++)
                #pragma unroll
                for (int nf = 0; nf < 4; nf++)
                    MMAF16(hacc[mf][nf], a[mf], b[nf >> 1][(nf & 1) * 2],
                           b[nf >> 1][(nf & 1) * 2 + 1]);
        }

        if (c & 1) {   // fold f16 pair-accumulators into f32 masters
            #pragma unroll
            for (int mf = 0; mf < 4; mf++)
                #pragma unroll
                for (int nf = 0; nf < 4; nf++) {
                    float2 lo = __half22float2(*(__half2*)&hacc[mf][nf][0]);
                    float2 hi = __half22float2(*(__half2*)&hacc[mf][nf][1]);
                    acc[mf][nf][0] += lo.x; acc[mf][nf][1] += lo.y;
                    acc[mf][nf][2] += hi.x; acc[mf][nf][3] += hi.y;
                }
        }
    }

    // ---------------- fused epilogue ----------------
    float ns = __ldg(nstr);
    int base_m = m0 + wm * 64;
    int base_n = n0 + wn * 32;
    int r0 = lane >> 2;
    int cpair = (lane & 3) * 2;

    #pragma unroll
    for (int mf = 0; mf < 4; mf++) {
        int mA = base_m + mf * 16 + r0;
        int mB = mA + 8;
        float nzA = __ldg(noise + mA) * ns;
        float nzB = __ldg(noise + mB) * ns;
        #pragma unroll
        for (int nf = 0; nf < 4; nf++) {
            int co = base_n + nf * 8 + cpair;
            float2 dd = *(const float2*)(g_d + img * 512 + co);
            float2 bb = *(const float2*)(conv_b + co);
            float v0 = acc[mf][nf][0] * dd.x + nzA + bb.x;
            float v1 = acc[mf][nf][1] * dd.y + nzA + bb.y;
            float v2 = acc[mf][nf][2] * dd.x + nzB + bb.x;
            float v3 = acc[mf][nf][3] * dd.y + nzB + bb.y;
            v0 = (v0 > 0.f ? v0 : 0.2f * v0) * LRELU_G;
            v1 = (v1 > 0.f ? v1 : 0.2f * v1) * LRELU_G;
            v2 = (v2 > 0.f ? v2 : 0.2f * v2) * LRELU_G;
            v3 = (v3 > 0.f ? v3 : 0.2f * v3) * LRELU_G;
            float2 oA = make_float2(fminf(fmaxf(v0, -256.f), 256.f),
                                    fminf(fmaxf(v1, -256.f), 256.f));
            float2 oB = make_float2(fminf(fmaxf(v2, -256.f), 256.f),
                                    fminf(fmaxf(v3, -256.f), 256.f));
            *(float2*)(out + (size_t)mA * 512 + co) = oA;
            *(float2*)(out + (size_t)mB * 512 + co) = oB;
        }
    }
}

// ---------------- launcher ----------------
// input order: x, dlatents, affine_w, affine_b, conv_w, conv_b, noise, noise_strength
extern "C" void kernel_launch(void* const* d_in, const int* in_sizes, int n_in,
                              void* d_out, int out_size) {
    const float* x   = (const float*)d_in[0];
    const float* dl  = (const float*)d_in[1];
    const float* aw  = (const float*)d_in[2];
    const float* ab  = (const float*)d_in[3];
    const float* cw  = (const float*)d_in[4];
    const float* cb  = (const float*)d_in[5];
    const float* noi = (const float*)d_in[6];
    const float* nst = (const float*)d_in[7];
    float* out = (float*)d_out;

    cudaFuncSetAttribute(k_conv, cudaFuncAttributeMaxDynamicSharedMemorySize, SMEM_TOTAL);

    k_affine<<<NB, 512>>>(dl, aw, ab);
    k_wsq<<<1024, 256>>>(cw);
    k_demod<<<dim3(NB, 4), 128>>>();
    k_xpk<<<2048, 256>>>(x);
    k_wpk<<<dim3(16, 8, 9), dim3(32, 8)>>>(cw);
    k_conv<<<(M_TOTAL / TM) * (COUTC / TN), CTHREADS, SMEM_TOTAL>>>(cb, noi, nst, out);
}